// round 2
// baseline (speedup 1.0000x reference)
#include <cuda_runtime.h>

// GaussianSoftmax: X[8,4096,16], sigma[1] -> softmax(exp(exp(-sqdist/sigma)), axis=2) [8,4096,4096]
//
// Design: block owns R=8 rows x full N=4096 cols. h=exp(g) tile kept in smem (128KB),
// X streamed in 8 j-tiles of 512 via register preload -> transposed smem (xt[f][j])
// so the dot product reads conflict-free LDS.128 quads and runs on packed fma.rn.f32x2.
// Row sums reduced in-block; phase 2 normalizes and writes coalesced STG.128.

#define BB 8
#define NN 4096
#define FF 16
#define RR 8      // rows per block
#define TT 256    // threads per block
#define JT 512    // j-tile
#define NTILES (NN / JT)
#define L2E 1.4426950408889634f

typedef unsigned long long ull;

struct Smem {
    float h[RR][NN];        // 131072 B  un-normalized exp(gaussian)
    float xt[FF][JT];       // 32768 B   transposed X tile: xt[f][j]
    float sqj[JT];          // 2048 B
    float xi[RR][FF];       // 512 B
    float sqi[RR];          // 32 B
    float inv[RR];          // 32 B
    float part[TT / 32][4]; // 128 B  per-warp row-sum partials
};

__device__ __forceinline__ ull ffma2(ull a, ull b, ull c) {
    ull d; asm("fma.rn.f32x2 %0, %1, %2, %3;" : "=l"(d) : "l"(a), "l"(b), "l"(c)); return d;
}
__device__ __forceinline__ ull fadd2(ull a, ull b) {
    ull d; asm("add.rn.f32x2 %0, %1, %2;" : "=l"(d) : "l"(a), "l"(b)); return d;
}
__device__ __forceinline__ ull fmul2(ull a, ull b) {
    ull d; asm("mul.rn.f32x2 %0, %1, %2;" : "=l"(d) : "l"(a), "l"(b)); return d;
}
__device__ __forceinline__ ull pk(float a, float b) {
    ull d; asm("mov.b64 %0, {%1, %2};" : "=l"(d) : "f"(a), "f"(b)); return d;
}
__device__ __forceinline__ float2 upk(ull v) {
    float2 r; asm("mov.b64 {%0, %1}, %2;" : "=f"(r.x), "=f"(r.y) : "l"(v)); return r;
}
__device__ __forceinline__ float ex2f(float x) {
    float r; asm("ex2.approx.f32 %0, %1;" : "=f"(r) : "f"(x)); return r;
}

__global__ void __launch_bounds__(TT, 1)
GaussianSoftmax_67714454389333_kernel(const float* __restrict__ X,
                                      const float* __restrict__ sigma,
                                      float* __restrict__ out) {
    extern __shared__ char smem_raw[];
    Smem& sm = *reinterpret_cast<Smem*>(smem_raw);

    const int tid = threadIdx.x;
    const int b = blockIdx.y;
    const int i0 = blockIdx.x * RR;
    const int rg = tid >> 7;          // row-group 0/1 -> rows rg*4 .. rg*4+3
    const int qt = tid & 127;         // quad id within row-group (j0 = qt*4 in tile)
    const int rg4 = rg * 4;

    const float* Xb = X + (size_t)b * NN * FF;
    const float4* Xb4 = reinterpret_cast<const float4*>(Xb);

    // ---- constants ----
    const float sg = sigma[0];
    const float cexp = -L2E / sg;         // g = exp2(cexp * sqdist)
    const ull CE = pk(cexp, cexp);
    const ull M2 = pk(-2.0f, -2.0f);

    // ---- phase 0: load the 8 query rows, compute sq_i ----
    if (tid < RR * FF) {
        int r = tid >> 4, f = tid & 15;
        sm.xi[r][f] = Xb[(size_t)(i0 + r) * FF + f];
    }
    __syncthreads();
    if (tid < RR) {
        float s = 0.f;
        #pragma unroll
        for (int f = 0; f < FF; ++f) { float v = sm.xi[tid][f]; s = fmaf(v, v, s); }
        sm.sqi[tid] = s;
    }
    __syncthreads();

    // per-thread duplicated x_i (rows of my row-group) and sq_i pairs
    ull xid[4][FF];
    ull sqid[4];
    #pragma unroll
    for (int r = 0; r < 4; ++r) {
        #pragma unroll
        for (int f = 0; f < FF; ++f) {
            float v = sm.xi[rg4 + r][f];
            xid[r][f] = pk(v, v);
        }
        float sv = sm.sqi[rg4 + r];
        sqid[r] = pk(sv, sv);
    }

    float rsum[4] = {0.f, 0.f, 0.f, 0.f};

    // ---- register preload of tile 0 (2 j-rows per thread) ----
    float4 A[4], Bv[4];
    {
        const float4* p = Xb4;  // tile 0
        #pragma unroll
        for (int k = 0; k < 4; ++k) A[k] = p[(size_t)tid * 4 + k];
        #pragma unroll
        for (int k = 0; k < 4; ++k) Bv[k] = p[(size_t)(tid + 256) * 4 + k];
    }

    // ---- main loop over 8 j-tiles ----
    #pragma unroll 1
    for (int t = 0; t < NTILES; ++t) {
        __syncthreads();  // previous tile's xt reads complete

        // store preloaded rows transposed + sq_j
        {
            float sa = 0.f, sb = 0.f;
            #pragma unroll
            for (int k = 0; k < 4; ++k) {
                sm.xt[4 * k + 0][tid] = A[k].x;
                sm.xt[4 * k + 1][tid] = A[k].y;
                sm.xt[4 * k + 2][tid] = A[k].z;
                sm.xt[4 * k + 3][tid] = A[k].w;
                sa = fmaf(A[k].x, A[k].x, sa); sa = fmaf(A[k].y, A[k].y, sa);
                sa = fmaf(A[k].z, A[k].z, sa); sa = fmaf(A[k].w, A[k].w, sa);
                sm.xt[4 * k + 0][tid + 256] = Bv[k].x;
                sm.xt[4 * k + 1][tid + 256] = Bv[k].y;
                sm.xt[4 * k + 2][tid + 256] = Bv[k].z;
                sm.xt[4 * k + 3][tid + 256] = Bv[k].w;
                sb = fmaf(Bv[k].x, Bv[k].x, sb); sb = fmaf(Bv[k].y, Bv[k].y, sb);
                sb = fmaf(Bv[k].z, Bv[k].z, sb); sb = fmaf(Bv[k].w, Bv[k].w, sb);
            }
            sm.sqj[tid] = sa;
            sm.sqj[tid + 256] = sb;
        }
        __syncthreads();  // xt/sqj ready

        // kick off next tile's loads (latency hidden behind compute)
        if (t + 1 < NTILES) {
            const float4* p = Xb4 + (size_t)(t + 1) * JT * 4;
            #pragma unroll
            for (int k = 0; k < 4; ++k) A[k] = p[(size_t)tid * 4 + k];
            #pragma unroll
            for (int k = 0; k < 4; ++k) Bv[k] = p[(size_t)(tid + 256) * 4 + k];
        }

        // ---- compute: 4 rows x 4 cols per thread ----
        {
            const int jq = qt << 2;
            ull aL0 = 0, aL1 = 0, aL2 = 0, aL3 = 0;
            ull aH0 = 0, aH1 = 0, aH2 = 0, aH3 = 0;
            #pragma unroll
            for (int f = 0; f < FF; ++f) {
                ulonglong2 xj = *reinterpret_cast<const ulonglong2*>(&sm.xt[f][jq]);
                aL0 = ffma2(xj.x, xid[0][f], aL0); aH0 = ffma2(xj.y, xid[0][f], aH0);
                aL1 = ffma2(xj.x, xid[1][f], aL1); aH1 = ffma2(xj.y, xid[1][f], aH1);
                aL2 = ffma2(xj.x, xid[2][f], aL2); aH2 = ffma2(xj.y, xid[2][f], aH2);
                aL3 = ffma2(xj.x, xid[3][f], aL3); aH3 = ffma2(xj.y, xid[3][f], aH3);
            }
            ulonglong2 sj = *reinterpret_cast<const ulonglong2*>(&sm.sqj[jq]);
            const int col0 = t * JT + jq;

            #pragma unroll
            for (int r = 0; r < 4; ++r) {
                ull aL = (r == 0) ? aL0 : (r == 1) ? aL1 : (r == 2) ? aL2 : aL3;
                ull aH = (r == 0) ? aH0 : (r == 1) ? aH1 : (r == 2) ? aH2 : aH3;
                ull sL = fadd2(sj.x, sqid[r]);
                ull sH = fadd2(sj.y, sqid[r]);
                ull dL = ffma2(aL, M2, sL);     // sqdist = sq_i + sq_j - 2*inner
                ull dH = ffma2(aH, M2, sH);
                ull tL = fmul2(dL, CE);
                ull tH = fmul2(dH, CE);
                float2 lo = upk(tL), hi = upk(tH);
                float g0 = ex2f(lo.x), g1 = ex2f(lo.y);
                float g2 = ex2f(hi.x), g3 = ex2f(hi.y);
                float h0 = ex2f(g0 * L2E), h1 = ex2f(g1 * L2E);
                float h2 = ex2f(g2 * L2E), h3 = ex2f(g3 * L2E);
                rsum[r] += (h0 + h1) + (h2 + h3);
                float4 hv = make_float4(h0, h1, h2, h3);
                *reinterpret_cast<float4*>(&sm.h[rg4 + r][col0]) = hv;
            }
        }
    }

    // ---- row-sum reduction ----
    #pragma unroll
    for (int r = 0; r < 4; ++r) {
        float v = rsum[r];
        v += __shfl_xor_sync(0xffffffffu, v, 16);
        v += __shfl_xor_sync(0xffffffffu, v, 8);
        v += __shfl_xor_sync(0xffffffffu, v, 4);
        v += __shfl_xor_sync(0xffffffffu, v, 2);
        v += __shfl_xor_sync(0xffffffffu, v, 1);
        if ((tid & 31) == 0) sm.part[tid >> 5][r] = v;
    }
    __syncthreads();
    if (tid < RR) {
        int rgg = tid >> 2, rl = tid & 3;
        float s = sm.part[rgg * 4 + 0][rl] + sm.part[rgg * 4 + 1][rl] +
                  sm.part[rgg * 4 + 2][rl] + sm.part[rgg * 4 + 3][rl];
        sm.inv[tid] = 1.0f / s;
    }
    __syncthreads();

    // ---- phase 2: normalize + coalesced store ----
    float* outB = out + ((size_t)b * NN + i0) * NN;
    #pragma unroll 4
    for (int it = 0; it < (RR * NN / 4) / TT; ++it) {  // 32 iterations
        int c = it * TT + tid;
        int r = c >> 10;            // 1024 float4 per row
        int jq = c & 1023;
        float inv = sm.inv[r];
        float4 hv = *reinterpret_cast<const float4*>(&sm.h[r][jq << 2]);
        hv.x *= inv; hv.y *= inv; hv.z *= inv; hv.w *= inv;
        *reinterpret_cast<float4*>(&outB[(size_t)r * NN + (jq << 2)]) = hv;
    }
}

extern "C" void kernel_launch(void* const* d_in, const int* in_sizes, int n_in,
                              void* d_out, int out_size) {
    const float* X = (const float*)d_in[0];
    const float* sigma = (const float*)d_in[1];
    float* out = (float*)d_out;

    cudaFuncSetAttribute(GaussianSoftmax_67714454389333_kernel,
                         cudaFuncAttributeMaxDynamicSharedMemorySize,
                         (int)sizeof(Smem));

    dim3 grid(NN / RR, BB);   // (512, 8)
    GaussianSoftmax_67714454389333_kernel<<<grid, TT, sizeof(Smem)>>>(X, sigma, out);
}

// round 3
// speedup vs baseline: 1.0782x; 1.0782x over previous
#include <cuda_runtime.h>
#include <cuda_fp16.h>

// GaussianSoftmax: X[8,4096,16], sigma[1] -> softmax(exp(exp(-sqdist/sigma)), axis=2) [8,4096,4096]
//
// R3 design: CTA owns 16 rows x 4096 cols, T=512.
//  - X j-tiles of 512 loaded with fully-coalesced chunked LDG (4 threads per 64B row),
//    transposed into padded smem xt[16][516] (pad kills the 4-way STS bank conflict).
//  - xi pairs pre-packed (v,v) in smem (xip); dot product = packed fma.rn.f32x2 with
//    broadcast LDS of xi (no 128-reg xid array, no per-tile repack MOVs).
//  - h = exp(exp(-sqdist/sigma)) stored in smem as fp16 (halves the h round-trip bytes);
//    row sums accumulated in fp32 before rounding.
//  - phase 2 normalizes from fp16 h and writes coalesced STG.128.

#define BB 8
#define NN 4096
#define FF 16
#define RR 16     // rows per block
#define TT 512    // threads per block
#define JT 512    // j-tile
#define PAD 4
#define NTILES (NN / JT)
#define L2E 1.4426950408889634f

typedef unsigned long long ull;

struct Smem {
    unsigned h16[RR][NN / 2];   // 131072 B  un-normalized h as half2 pairs
    float xt[FF][JT + PAD];     // 33024 B   transposed X tile (padded)
    float sqj[JT];              // 2048 B
    ull   xip[FF * RR];         // 2048 B    packed (xi,xi), index f*16+r
    ull   sqip[RR];             // 128 B     packed (sqi,sqi)
    float xi[RR][FF];           // 1024 B
    float inv[RR];              // 64 B
    float part[TT / 32][4];     // 256 B
};

__device__ __forceinline__ ull ffma2(ull a, ull b, ull c) {
    ull d; asm("fma.rn.f32x2 %0, %1, %2, %3;" : "=l"(d) : "l"(a), "l"(b), "l"(c)); return d;
}
__device__ __forceinline__ ull fadd2(ull a, ull b) {
    ull d; asm("add.rn.f32x2 %0, %1, %2;" : "=l"(d) : "l"(a), "l"(b)); return d;
}
__device__ __forceinline__ ull fmul2(ull a, ull b) {
    ull d; asm("mul.rn.f32x2 %0, %1, %2;" : "=l"(d) : "l"(a), "l"(b)); return d;
}
__device__ __forceinline__ ull pk(float a, float b) {
    ull d; asm("mov.b64 %0, {%1, %2};" : "=l"(d) : "f"(a), "f"(b)); return d;
}
__device__ __forceinline__ float2 upk(ull v) {
    float2 r; asm("mov.b64 {%0, %1}, %2;" : "=f"(r.x), "=f"(r.y) : "l"(v)); return r;
}
__device__ __forceinline__ float ex2f(float x) {
    float r; asm("ex2.approx.f32 %0, %1;" : "=f"(r) : "f"(x)); return r;
}
__device__ __forceinline__ unsigned pkh2(float a, float b) {
    __half2 h = __floats2half2_rn(a, b);
    return *reinterpret_cast<unsigned*>(&h);
}

__global__ void __launch_bounds__(TT, 1)
GaussianSoftmax_67714454389333_kernel(const float* __restrict__ X,
                                      const float* __restrict__ sigma,
                                      float* __restrict__ out) {
    extern __shared__ char smem_raw[];
    Smem& sm = *reinterpret_cast<Smem*>(smem_raw);

    const int tid = threadIdx.x;
    const int b = blockIdx.y;
    const int i0 = blockIdx.x * RR;
    const int rg = tid >> 7;          // row-group 0..3 -> rows rg*4 .. rg*4+3
    const int qt = tid & 127;         // col-quad within tile
    const int rg4 = rg * 4;

    const float* Xb = X + (size_t)b * NN * FF;
    const float4* Xb4 = reinterpret_cast<const float4*>(Xb);

    // ---- preload tile 0 (coalesced: 4 threads per 64B j-row) ----
    float4 A[4];
    #pragma unroll
    for (int k = 0; k < 4; ++k) A[k] = Xb4[k * 512 + tid];

    // ---- constants ----
    const float sg = sigma[0];
    const float cexp = -L2E / sg;          // g = exp2(cexp * sqdist)
    const ull CE = pk(cexp, cexp);
    const ull M2 = pk(-2.0f, -2.0f);

    // ---- phase 0: query rows -> xi, then packed xip / sqip ----
    if (tid < RR * FF) {
        int r = tid >> 4, f = tid & 15;
        sm.xi[r][f] = Xb[(size_t)(i0 + r) * FF + f];
    }
    __syncthreads();
    if (tid < RR) {
        float s = 0.f;
        #pragma unroll
        for (int f = 0; f < FF; ++f) { float v = sm.xi[tid][f]; s = fmaf(v, v, s); }
        sm.sqip[tid] = pk(s, s);
    }
    if (tid >= 256) {
        int idx = tid - 256;
        int r = idx & 15, f = idx >> 4;
        float v = sm.xi[r][f];
        sm.xip[f * 16 + r] = pk(v, v);
    }
    __syncthreads();

    // loop-invariant sq_i pairs for my 4 rows (broadcast LDS, 8 regs)
    ull sqid[4];
    {
        ulonglong2 s0 = *reinterpret_cast<const ulonglong2*>(&sm.sqip[rg4]);
        ulonglong2 s1 = *reinterpret_cast<const ulonglong2*>(&sm.sqip[rg4 + 2]);
        sqid[0] = s0.x; sqid[1] = s0.y; sqid[2] = s1.x; sqid[3] = s1.y;
    }

    float rsum[4] = {0.f, 0.f, 0.f, 0.f};
    const int jq = qt << 2;

    // ---- main loop over 8 j-tiles ----
    #pragma unroll 1
    for (int t = 0; t < NTILES; ++t) {
        __syncthreads();  // previous tile's xt/sqj reads complete

        // store preloaded chunks transposed + row sq_j
        {
            const int c = tid & 3;          // f-chunk
            const int jr = tid >> 2;        // row base within k-group
            #pragma unroll
            for (int k = 0; k < 4; ++k) {
                int j = k * 128 + jr;       // local j-row
                sm.xt[4 * c + 0][j] = A[k].x;
                sm.xt[4 * c + 1][j] = A[k].y;
                sm.xt[4 * c + 2][j] = A[k].z;
                sm.xt[4 * c + 3][j] = A[k].w;
                float s = fmaf(A[k].x, A[k].x, fmaf(A[k].y, A[k].y,
                          fmaf(A[k].z, A[k].z, A[k].w * A[k].w)));
                s += __shfl_xor_sync(0xffffffffu, s, 1);
                s += __shfl_xor_sync(0xffffffffu, s, 2);
                if (c == 0) sm.sqj[j] = s;
            }
        }
        __syncthreads();  // xt/sqj ready

        // kick off next tile's loads
        if (t + 1 < NTILES) {
            const float4* p = Xb4 + (size_t)(t + 1) * 2048;
            #pragma unroll
            for (int k = 0; k < 4; ++k) A[k] = p[k * 512 + tid];
        }

        // ---- dot products: 4 rows x 4 cols per thread, packed f32x2 ----
        ull aL[4] = {0, 0, 0, 0};
        ull aH[4] = {0, 0, 0, 0};
        #pragma unroll
        for (int f = 0; f < FF; ++f) {
            ulonglong2 q0 = *reinterpret_cast<const ulonglong2*>(&sm.xip[f * 16 + rg4]);
            ulonglong2 q1 = *reinterpret_cast<const ulonglong2*>(&sm.xip[f * 16 + rg4 + 2]);
            ulonglong2 xj = *reinterpret_cast<const ulonglong2*>(&sm.xt[f][jq]);
            aL[0] = ffma2(xj.x, q0.x, aL[0]); aH[0] = ffma2(xj.y, q0.x, aH[0]);
            aL[1] = ffma2(xj.x, q0.y, aL[1]); aH[1] = ffma2(xj.y, q0.y, aH[1]);
            aL[2] = ffma2(xj.x, q1.x, aL[2]); aH[2] = ffma2(xj.y, q1.x, aH[2]);
            aL[3] = ffma2(xj.x, q1.y, aL[3]); aH[3] = ffma2(xj.y, q1.y, aH[3]);
        }

        // ---- epilogue: sqdist -> double exp -> fp16 h + fp32 row sums ----
        {
            ulonglong2 sj = *reinterpret_cast<const ulonglong2*>(&sm.sqj[jq]);
            const int colh = (t * JT + jq) >> 1;   // half2 index
            #pragma unroll
            for (int r = 0; r < 4; ++r) {
                ull sL = fadd2(sj.x, sqid[r]);
                ull sH = fadd2(sj.y, sqid[r]);
                ull dL = ffma2(aL[r], M2, sL);     // sq_i + sq_j - 2*inner
                ull dH = ffma2(aH[r], M2, sH);
                ull tL = fmul2(dL, CE);
                ull tH = fmul2(dH, CE);
                float2 lo = upk(tL), hi = upk(tH);
                float g0 = ex2f(lo.x), g1 = ex2f(lo.y);
                float g2 = ex2f(hi.x), g3 = ex2f(hi.y);
                float h0 = ex2f(g0 * L2E), h1 = ex2f(g1 * L2E);
                float h2 = ex2f(g2 * L2E), h3 = ex2f(g3 * L2E);
                rsum[r] += (h0 + h1) + (h2 + h3);
                uint2 hv = make_uint2(pkh2(h0, h1), pkh2(h2, h3));
                *reinterpret_cast<uint2*>(&sm.h16[rg4 + r][colh]) = hv;
            }
        }
    }

    // ---- row-sum reduction ----
    #pragma unroll
    for (int r = 0; r < 4; ++r) {
        float v = rsum[r];
        v += __shfl_xor_sync(0xffffffffu, v, 16);
        v += __shfl_xor_sync(0xffffffffu, v, 8);
        v += __shfl_xor_sync(0xffffffffu, v, 4);
        v += __shfl_xor_sync(0xffffffffu, v, 2);
        v += __shfl_xor_sync(0xffffffffu, v, 1);
        if ((tid & 31) == 0) sm.part[tid >> 5][r] = v;
    }
    __syncthreads();
    if (tid < RR) {
        int rgg = tid >> 2, rl = tid & 3;
        float s = sm.part[rgg * 4 + 0][rl] + sm.part[rgg * 4 + 1][rl] +
                  sm.part[rgg * 4 + 2][rl] + sm.part[rgg * 4 + 3][rl];
        sm.inv[tid] = 1.0f / s;
    }
    __syncthreads();

    // ---- phase 2: normalize fp16 h, coalesced STG.128 ----
    float* outB = out + ((size_t)b * NN + i0) * NN;
    #pragma unroll 4
    for (int it = 0; it < (RR * NN / 4) / TT; ++it) {   // 32 iterations
        int c = it * TT + tid;
        int r = c >> 10;            // 1024 float4 per row
        int j4 = c & 1023;
        float inv = sm.inv[r];
        uint2 v = *reinterpret_cast<const uint2*>(&sm.h16[r][j4 * 2]);
        float2 f0 = __half22float2(*reinterpret_cast<__half2*>(&v.x));
        float2 f1 = __half22float2(*reinterpret_cast<__half2*>(&v.y));
        float4 o = make_float4(f0.x * inv, f0.y * inv, f1.x * inv, f1.y * inv);
        *reinterpret_cast<float4*>(&outB[(size_t)r * NN + j4 * 4]) = o;
    }
}

extern "C" void kernel_launch(void* const* d_in, const int* in_sizes, int n_in,
                              void* d_out, int out_size) {
    const float* X = (const float*)d_in[0];
    const float* sigma = (const float*)d_in[1];
    float* out = (float*)d_out;

    cudaFuncSetAttribute(GaussianSoftmax_67714454389333_kernel,
                         cudaFuncAttributeMaxDynamicSharedMemorySize,
                         (int)sizeof(Smem));

    dim3 grid(NN / RR, BB);   // (256, 8)
    GaussianSoftmax_67714454389333_kernel<<<grid, TT, sizeof(Smem)>>>(X, sigma, out);
}

// round 4
// speedup vs baseline: 1.1456x; 1.0625x over previous
#include <cuda_runtime.h>
#include <cuda_fp16.h>

// GaussianSoftmax: X[8,4096,16], sigma[1] -> softmax(exp(exp(-sqdist/sigma)), axis=2) [8,4096,4096]
//
// R4 design: RR=8 rows/CTA, T=256, smem ~101KB -> 2 CTAs/SM (two independent barrier
// domains; syncs and the phase-2 store burst of one CTA overlap the mainloop of the other).
//  - X j-tiles of 512: coalesced chunked LDG (4 threads per 64B row) -> padded transposed
//    smem xt[16][516].
//  - dot product: packed fma.rn.f32x2, xi pairs broadcast from smem (xip).
//  - h kept in smem as fp16 (64KB), fp32 row sums; phase 2 normalizes + st.global.cs.

#define BB 8
#define NN 4096
#define FF 16
#define RR 8      // rows per block
#define TT 256    // threads per block
#define JT 512    // j-tile
#define PAD 4
#define NTILES (NN / JT)
#define L2E 1.4426950408889634f

typedef unsigned long long ull;

struct Smem {
    unsigned h16[RR][NN / 2];   // 65536 B   un-normalized h as half2 pairs
    float xt[FF][JT + PAD];     // 33024 B   transposed X tile (padded)
    float sqj[JT];              // 2048 B
    ull   xip[FF * RR];         // 1024 B    packed (xi,xi), index f*8+r
    ull   sqip[RR];             // 64 B      packed (sqi,sqi)
    float xi[RR][FF];           // 512 B
    float inv[RR];              // 32 B
    float part[TT / 32][4];     // 128 B
};  // ~102 KB -> 2 CTAs/SM

__device__ __forceinline__ ull ffma2(ull a, ull b, ull c) {
    ull d; asm("fma.rn.f32x2 %0, %1, %2, %3;" : "=l"(d) : "l"(a), "l"(b), "l"(c)); return d;
}
__device__ __forceinline__ ull fadd2(ull a, ull b) {
    ull d; asm("add.rn.f32x2 %0, %1, %2;" : "=l"(d) : "l"(a), "l"(b)); return d;
}
__device__ __forceinline__ ull fmul2(ull a, ull b) {
    ull d; asm("mul.rn.f32x2 %0, %1, %2;" : "=l"(d) : "l"(a), "l"(b)); return d;
}
__device__ __forceinline__ ull pk(float a, float b) {
    ull d; asm("mov.b64 %0, {%1, %2};" : "=l"(d) : "f"(a), "f"(b)); return d;
}
__device__ __forceinline__ float2 upk(ull v) {
    float2 r; asm("mov.b64 {%0, %1}, %2;" : "=f"(r.x), "=f"(r.y) : "l"(v)); return r;
}
__device__ __forceinline__ float ex2f(float x) {
    float r; asm("ex2.approx.f32 %0, %1;" : "=f"(r) : "f"(x)); return r;
}
__device__ __forceinline__ unsigned pkh2(float a, float b) {
    __half2 h = __floats2half2_rn(a, b);
    return *reinterpret_cast<unsigned*>(&h);
}
__device__ __forceinline__ void stcs4(float* p, float4 v) {
    asm volatile("st.global.cs.v4.f32 [%0], {%1, %2, %3, %4};"
                 :: "l"(p), "f"(v.x), "f"(v.y), "f"(v.z), "f"(v.w) : "memory");
}

__global__ void __launch_bounds__(TT, 2)
GaussianSoftmax_67714454389333_kernel(const float* __restrict__ X,
                                      const float* __restrict__ sigma,
                                      float* __restrict__ out) {
    extern __shared__ char smem_raw[];
    Smem& sm = *reinterpret_cast<Smem*>(smem_raw);

    const int tid = threadIdx.x;
    const int b = blockIdx.y;
    const int i0 = blockIdx.x * RR;
    const int rg = tid >> 7;          // row-group 0..1 -> rows rg*4 .. rg*4+3
    const int qt = tid & 127;         // col-quad within tile
    const int rg4 = rg * 4;

    const float* Xb = X + (size_t)b * NN * FF;
    const float4* Xb4 = reinterpret_cast<const float4*>(Xb);

    // ---- preload tile 0 (coalesced: 4 threads per 64B j-row; 8 chunks) ----
    float4 A[8];
    #pragma unroll
    for (int k = 0; k < 8; ++k) A[k] = Xb4[k * 256 + tid];

    // ---- constants ----
    const float sg = sigma[0];
    const float cexp = -L2E / sg;          // g = exp2(cexp * sqdist)
    const ull CE = pk(cexp, cexp);
    const ull M2 = pk(-2.0f, -2.0f);

    // ---- phase 0: query rows -> xi, then packed xip / sqip ----
    if (tid < RR * FF) {
        int r = tid >> 4, f = tid & 15;
        sm.xi[r][f] = Xb[(size_t)(i0 + r) * FF + f];
    }
    __syncthreads();
    if (tid < RR) {
        float s = 0.f;
        #pragma unroll
        for (int f = 0; f < FF; ++f) { float v = sm.xi[tid][f]; s = fmaf(v, v, s); }
        sm.sqip[tid] = pk(s, s);
    }
    if (tid >= 128 && tid < 256) {
        int idx = tid - 128;
        int r = idx & 7, f = idx >> 3;
        float v = sm.xi[r][f];
        sm.xip[f * 8 + r] = pk(v, v);
    }
    __syncthreads();

    // loop-invariant sq_i pairs for my 4 rows (broadcast LDS)
    ull sqid[4];
    {
        ulonglong2 s0 = *reinterpret_cast<const ulonglong2*>(&sm.sqip[rg4]);
        ulonglong2 s1 = *reinterpret_cast<const ulonglong2*>(&sm.sqip[rg4 + 2]);
        sqid[0] = s0.x; sqid[1] = s0.y; sqid[2] = s1.x; sqid[3] = s1.y;
    }

    float rsum[4] = {0.f, 0.f, 0.f, 0.f};
    const int jq = qt << 2;

    // ---- main loop over 8 j-tiles ----
    #pragma unroll 1
    for (int t = 0; t < NTILES; ++t) {
        __syncthreads();  // previous tile's xt/sqj reads complete

        // store preloaded chunks transposed + row sq_j
        {
            const int c = tid & 3;          // f-chunk
            const int jr = tid >> 2;        // j-row within k-group (0..63)
            #pragma unroll
            for (int k = 0; k < 8; ++k) {
                int j = k * 64 + jr;        // local j-row
                sm.xt[4 * c + 0][j] = A[k].x;
                sm.xt[4 * c + 1][j] = A[k].y;
                sm.xt[4 * c + 2][j] = A[k].z;
                sm.xt[4 * c + 3][j] = A[k].w;
                float s = fmaf(A[k].x, A[k].x, fmaf(A[k].y, A[k].y,
                          fmaf(A[k].z, A[k].z, A[k].w * A[k].w)));
                s += __shfl_xor_sync(0xffffffffu, s, 1);
                s += __shfl_xor_sync(0xffffffffu, s, 2);
                if (c == 0) sm.sqj[j] = s;
            }
        }
        __syncthreads();  // xt/sqj ready

        // kick off next tile's loads
        if (t + 1 < NTILES) {
            const float4* p = Xb4 + (size_t)(t + 1) * 2048;
            #pragma unroll
            for (int k = 0; k < 8; ++k) A[k] = p[k * 256 + tid];
        }

        // ---- dot products: 4 rows x 4 cols per thread, packed f32x2 ----
        ull aL[4] = {0, 0, 0, 0};
        ull aH[4] = {0, 0, 0, 0};
        #pragma unroll
        for (int f = 0; f < FF; ++f) {
            ulonglong2 q0 = *reinterpret_cast<const ulonglong2*>(&sm.xip[f * 8 + rg4]);
            ulonglong2 q1 = *reinterpret_cast<const ulonglong2*>(&sm.xip[f * 8 + rg4 + 2]);
            ulonglong2 xj = *reinterpret_cast<const ulonglong2*>(&sm.xt[f][jq]);
            aL[0] = ffma2(xj.x, q0.x, aL[0]); aH[0] = ffma2(xj.y, q0.x, aH[0]);
            aL[1] = ffma2(xj.x, q0.y, aL[1]); aH[1] = ffma2(xj.y, q0.y, aH[1]);
            aL[2] = ffma2(xj.x, q1.x, aL[2]); aH[2] = ffma2(xj.y, q1.x, aH[2]);
            aL[3] = ffma2(xj.x, q1.y, aL[3]); aH[3] = ffma2(xj.y, q1.y, aH[3]);
        }

        // ---- epilogue: sqdist -> double exp -> fp16 h + fp32 row sums ----
        {
            ulonglong2 sj = *reinterpret_cast<const ulonglong2*>(&sm.sqj[jq]);
            const int colh = (t * JT + jq) >> 1;   // half2 index
            #pragma unroll
            for (int r = 0; r < 4; ++r) {
                ull sL = fadd2(sj.x, sqid[r]);
                ull sH = fadd2(sj.y, sqid[r]);
                ull dL = ffma2(aL[r], M2, sL);     // sq_i + sq_j - 2*inner
                ull dH = ffma2(aH[r], M2, sH);
                ull tL = fmul2(dL, CE);
                ull tH = fmul2(dH, CE);
                float2 lo = upk(tL), hi = upk(tH);
                float g0 = ex2f(lo.x), g1 = ex2f(lo.y);
                float g2 = ex2f(hi.x), g3 = ex2f(hi.y);
                float h0 = ex2f(g0 * L2E), h1 = ex2f(g1 * L2E);
                float h2 = ex2f(g2 * L2E), h3 = ex2f(g3 * L2E);
                rsum[r] += (h0 + h1) + (h2 + h3);
                uint2 hv = make_uint2(pkh2(h0, h1), pkh2(h2, h3));
                *reinterpret_cast<uint2*>(&sm.h16[rg4 + r][colh]) = hv;
            }
        }
    }

    // ---- row-sum reduction ----
    #pragma unroll
    for (int r = 0; r < 4; ++r) {
        float v = rsum[r];
        v += __shfl_xor_sync(0xffffffffu, v, 16);
        v += __shfl_xor_sync(0xffffffffu, v, 8);
        v += __shfl_xor_sync(0xffffffffu, v, 4);
        v += __shfl_xor_sync(0xffffffffu, v, 2);
        v += __shfl_xor_sync(0xffffffffu, v, 1);
        if ((tid & 31) == 0) sm.part[tid >> 5][r] = v;
    }
    __syncthreads();
    if (tid < RR) {
        int rgg = tid >> 2, rl = tid & 3;
        float s = sm.part[rgg * 4 + 0][rl] + sm.part[rgg * 4 + 1][rl] +
                  sm.part[rgg * 4 + 2][rl] + sm.part[rgg * 4 + 3][rl];
        sm.inv[tid] = 1.0f / s;
    }
    __syncthreads();

    // ---- phase 2: normalize fp16 h, coalesced streaming STG.128 ----
    float* outB = out + ((size_t)b * NN + i0) * NN;
    #pragma unroll 4
    for (int it = 0; it < (RR * NN / 4) / TT; ++it) {   // 32 iterations
        int c = it * TT + tid;
        int r = c >> 10;            // 1024 float4 per row
        int j4 = c & 1023;
        float inv = sm.inv[r];
        uint2 v = *reinterpret_cast<const uint2*>(&sm.h16[r][j4 * 2]);
        float2 f0 = __half22float2(*reinterpret_cast<__half2*>(&v.x));
        float2 f1 = __half22float2(*reinterpret_cast<__half2*>(&v.y));
        float4 o = make_float4(f0.x * inv, f0.y * inv, f1.x * inv, f1.y * inv);
        stcs4(&outB[(size_t)r * NN + j4 * 4], o);
    }
}

extern "C" void kernel_launch(void* const* d_in, const int* in_sizes, int n_in,
                              void* d_out, int out_size) {
    const float* X = (const float*)d_in[0];
    const float* sigma = (const float*)d_in[1];
    float* out = (float*)d_out;

    cudaFuncSetAttribute(GaussianSoftmax_67714454389333_kernel,
                         cudaFuncAttributeMaxDynamicSharedMemorySize,
                         (int)sizeof(Smem));

    dim3 grid(NN / RR, BB);   // (512, 8)
    GaussianSoftmax_67714454389333_kernel<<<grid, TT, sizeof(Smem)>>>(X, sigma, out);
}

// round 6
// speedup vs baseline: 1.1911x; 1.0397x over previous
#include <cuda_runtime.h>
#include <cuda_fp16.h>

// GaussianSoftmax: X[8,4096,16], sigma[1] -> softmax(exp(exp(-sqdist/sigma)), axis=2) [8,4096,4096]
//
// R5: T=128, RR=8, 2 CTAs/SM (reg cap 256). xi held in REGISTERS for the whole
// kernel (8 rows x 16 f packed (v,v) = 128 regs) -> the per-tile xi broadcast LDS
// (32B/elem of L1 traffic) disappears. Thread computes 8 rows x 2 cols; xj is one
// LDS.64 per f (8B/elem total inner L1). -sqi/2 folded into accumulator init,
// cexp folded into epilogue FFMA2. h kept fp16 in smem; streaming STG.128 out.

#define BB 8
#define NN 4096
#define FF 16
#define RR 8      // rows per block (= rows per thread)
#define TT 128    // threads per block
#define JT 256    // j-tile
#define STRIDE 258  // xt row stride in floats (pad=2: conflict-free STS + LDS.64)
#define NTILES (NN / JT)
#define L2E 1.4426950408889634f

typedef unsigned long long ull;

struct Smem {
    unsigned h16[RR][NN / 2];   // 65536 B   un-normalized h as half2
    float xt[FF][STRIDE];       // 16512 B   transposed X tile
    float sqj[JT];              // 1024 B
    ull   xip[FF * RR];         // 1024 B    packed (xi,xi), index f*8+r
    ull   sqip[RR];             // 64 B      packed (-sqi/2, -sqi/2)
    float xi[RR][FF];           // 512 B
    float inv[RR];              // 32 B
    float part[TT / 32][RR];    // 128 B
};  // ~84.9 KB -> 2 CTAs/SM

__device__ __forceinline__ ull ffma2(ull a, ull b, ull c) {
    ull d; asm("fma.rn.f32x2 %0, %1, %2, %3;" : "=l"(d) : "l"(a), "l"(b), "l"(c)); return d;
}
__device__ __forceinline__ ull fmul2(ull a, ull b) {
    ull d; asm("mul.rn.f32x2 %0, %1, %2;" : "=l"(d) : "l"(a), "l"(b)); return d;
}
__device__ __forceinline__ ull pk(float a, float b) {
    ull d; asm("mov.b64 %0, {%1, %2};" : "=l"(d) : "f"(a), "f"(b)); return d;
}
__device__ __forceinline__ float2 upk(ull v) {
    float2 r; asm("mov.b64 {%0, %1}, %2;" : "=f"(r.x), "=f"(r.y) : "l"(v)); return r;
}
__device__ __forceinline__ float ex2f(float x) {
    float r; asm("ex2.approx.f32 %0, %1;" : "=f"(r) : "f"(x)); return r;
}
__device__ __forceinline__ unsigned pkh2(float a, float b) {
    __half2 h = __floats2half2_rn(a, b);
    return *reinterpret_cast<unsigned*>(&h);
}
__device__ __forceinline__ void stcs4(float* p, float4 v) {
    asm volatile("st.global.cs.v4.f32 [%0], {%1, %2, %3, %4};"
                 :: "l"(p), "f"(v.x), "f"(v.y), "f"(v.z), "f"(v.w) : "memory");
}

__global__ void __launch_bounds__(TT, 2)
GaussianSoftmax_67714454389333_kernel(const float* __restrict__ X,
                                      const float* __restrict__ sigma,
                                      float* __restrict__ out) {
    extern __shared__ char smem_raw[];
    Smem& sm = *reinterpret_cast<Smem*>(smem_raw);

    const int tid = threadIdx.x;
    const int b = blockIdx.y;
    const int i0 = blockIdx.x * RR;

    const float* Xb = X + (size_t)b * NN * FF;
    const float4* Xb4 = reinterpret_cast<const float4*>(Xb);

    // ---- preload tile 0 (coalesced: 4 threads per 64B j-row; 8 chunks of 2KB) ----
    float4 A[8];
    #pragma unroll
    for (int k = 0; k < 8; ++k) A[k] = Xb4[k * 128 + tid];

    // ---- constants ----
    const float sg = sigma[0];
    const float cexp = -L2E / sg;              // e = cexp * sqdist; g = 2^e
    const ull CE  = pk(cexp, cexp);
    const ull CM2 = pk(-2.0f * cexp, -2.0f * cexp);

    // ---- phase 0: query rows -> xi, sqip, packed xip ----
    {
        int r = tid >> 4, f = tid & 15;        // 128 threads cover 8x16
        sm.xi[r][f] = Xb[(size_t)(i0 + r) * FF + f];
    }
    __syncthreads();
    if (tid < RR) {
        float s = 0.f;
        #pragma unroll
        for (int f = 0; f < FF; ++f) { float v = sm.xi[tid][f]; s = fmaf(v, v, s); }
        sm.sqip[tid] = pk(-0.5f * s, -0.5f * s);
    }
    {
        int r = tid & 7, f = tid >> 3;
        float v = sm.xi[r][f];
        sm.xip[f * 8 + r] = pk(v, v);
    }
    __syncthreads();

    // ---- hoist xi pairs + (-sqi/2) pairs into registers for the whole kernel ----
    ull xq[FF][RR];
    #pragma unroll
    for (int f = 0; f < FF; ++f)
        #pragma unroll
        for (int r = 0; r < RR; ++r)
            xq[f][r] = sm.xip[f * 8 + r];
    ull si[RR];
    #pragma unroll
    for (int r = 0; r < RR; ++r) si[r] = sm.sqip[r];

    ull acc[RR];
    #pragma unroll
    for (int r = 0; r < RR; ++r) acc[r] = si[r];
    float rsum[RR];
    #pragma unroll
    for (int r = 0; r < RR; ++r) rsum[r] = 0.f;

    const int jq = tid * 2;     // my 2 columns within the tile

    // ---- main loop over 16 j-tiles ----
    #pragma unroll 1
    for (int t = 0; t < NTILES; ++t) {
        __syncthreads();  // previous tile's xt/sqj reads complete

        // transpose preloaded chunks + row sq_j
        {
            const int c = tid & 3;          // f-chunk
            const int jr = tid >> 2;        // j-row within k-group (0..31)
            #pragma unroll
            for (int k = 0; k < 8; ++k) {
                int j = k * 32 + jr;
                sm.xt[4 * c + 0][j] = A[k].x;
                sm.xt[4 * c + 1][j] = A[k].y;
                sm.xt[4 * c + 2][j] = A[k].z;
                sm.xt[4 * c + 3][j] = A[k].w;
                float s = fmaf(A[k].x, A[k].x, fmaf(A[k].y, A[k].y,
                          fmaf(A[k].z, A[k].z, A[k].w * A[k].w)));
                s += __shfl_xor_sync(0xffffffffu, s, 1);
                s += __shfl_xor_sync(0xffffffffu, s, 2);
                if (c == 0) sm.sqj[j] = s;
            }
        }
        __syncthreads();  // xt/sqj ready

        // kick off next tile's loads
        if (t + 1 < NTILES) {
            const float4* p = Xb4 + (size_t)(t + 1) * 1024;
            #pragma unroll
            for (int k = 0; k < 8; ++k) A[k] = p[k * 128 + tid];
        }

        // ---- dot products: 8 rows x 2 cols, xi from registers ----
        #pragma unroll
        for (int f = 0; f < FF; ++f) {
            ull xj = *reinterpret_cast<const ull*>(&sm.xt[f][jq]);
            #pragma unroll
            for (int r = 0; r < RR; ++r)
                acc[r] = ffma2(xj, xq[f][r], acc[r]);
        }

        // ---- epilogue: e = CM2*acc + CE*sqj -> double exp -> fp16 h + row sums ----
        {
            ull sj = *reinterpret_cast<const ull*>(&sm.sqj[jq]);
            ull sjc = fmul2(sj, CE);
            const int colh = t * (JT / 2) + tid;
            #pragma unroll
            for (int r = 0; r < RR; ++r) {
                ull e2 = ffma2(acc[r], CM2, sjc);
                float2 e = upk(e2);
                float g0 = ex2f(e.x), g1 = ex2f(e.y);
                float h0 = ex2f(g0 * L2E), h1 = ex2f(g1 * L2E);
                rsum[r] += h0 + h1;
                sm.h16[r][colh] = pkh2(h0, h1);
                acc[r] = si[r];
            }
        }
    }

    // ---- row-sum reduction (4 warps) ----
    #pragma unroll
    for (int r = 0; r < RR; ++r) {
        float v = rsum[r];
        v += __shfl_xor_sync(0xffffffffu, v, 16);
        v += __shfl_xor_sync(0xffffffffu, v, 8);
        v += __shfl_xor_sync(0xffffffffu, v, 4);
        v += __shfl_xor_sync(0xffffffffu, v, 2);
        v += __shfl_xor_sync(0xffffffffu, v, 1);
        if ((tid & 31) == 0) sm.part[tid >> 5][r] = v;
    }
    __syncthreads();
    if (tid < RR) {
        float s = sm.part[0][tid] + sm.part[1][tid] +
                  sm.part[2][tid] + sm.part[3][tid];
        sm.inv[tid] = 1.0f / s;
    }
    __syncthreads();

    // ---- phase 2: normalize fp16 h, coalesced streaming STG.128 ----
    float* outB = out + ((size_t)b * NN + i0) * NN;
    #pragma unroll 4
    for (int it = 0; it < (RR * NN / 4) / TT; ++it) {   // 64 iterations
        int c = it * TT + tid;
        int r = c >> 10;            // 1024 float4 per row
        int j4 = c & 1023;
        float inv = sm.inv[r];
        uint2 v = *reinterpret_cast<const uint2*>(&sm.h16[r][j4 * 2]);
        float2 f0 = __half22float2(*reinterpret_cast<__half2*>(&v.x));
        float2 f1 = __half22float2(*reinterpret_cast<__half2*>(&v.y));
        float4 o = make_float4(f0.x * inv, f0.y * inv, f1.x * inv, f1.y * inv);
        stcs4(&outB[(size_t)r * NN + j4 * 4], o);
    }
}

extern "C" void kernel_launch(void* const* d_in, const int* in_sizes, int n_in,
                              void* d_out, int out_size) {
    const float* X = (const float*)d_in[0];
    const float* sigma = (const float*)d_in[1];
    float* out = (float*)d_out;

    cudaFuncSetAttribute(GaussianSoftmax_67714454389333_kernel,
                         cudaFuncAttributeMaxDynamicSharedMemorySize,
                         (int)sizeof(Smem));

    dim3 grid(NN / RR, BB);   // (512, 8)
    GaussianSoftmax_67714454389333_kernel<<<grid, TT, sizeof(Smem)>>>(X, sigma, out);
}

// round 7
// speedup vs baseline: 1.3283x; 1.1152x over previous
#include <cuda_runtime.h>
#include <cuda_fp16.h>

// GaussianSoftmax: X[8,4096,16], sigma[1] -> softmax(exp(exp(-sqdist/sigma)), axis=2) [8,4096,4096]
//
// R7 design: T=256, RR=8 rows/CTA, JT=256, 2 CTAs/SM.
//  - f-PAIRED f32x2: xq[fp][r] = (xi[r][2fp], xi[r][2fp+1]) -- natural float2, NO lane
//    duplication -> 64 regs (R5's 256-reg spill eliminated). acc lanes = even/odd-f
//    partial sums, combined with one add in the epilogue.
//  - X tiles arrive via double-buffered cp.async (LDGSTS) into xtp[fp][j] float2 rows:
//    no A-register preload, no transpose ALU, copy(t+1) overlaps compute(t).
//  - sq_j * cexp precomputed by a tiny pre-kernel into __device__ scratch, cp.async'd.
//  - h kept fp16 in smem; fp32 row sums; phase 2 normalizes + streaming STG.128.

#define BB 8
#define NN 4096
#define FF 16
#define RR 8
#define TT 256
#define JT 256
#define NT (NN / JT)
#define S2 260                       // xtp row stride in float2
#define L2E 1.4426950408889634f

typedef unsigned long long ull;

__device__ float g_sqc[BB * NN];     // cexp * ||x_j||^2

// smem byte offsets
#define H16_OFF 0                              // RR x NN/2 uint = 65536
#define XTP_ROW (S2 * 8)                       // 2080 B per fp row
#define XTP_BUF (8 * XTP_ROW)                  // 16640 B per buffer
#define XTP_OFF 65536                          // 2 buffers
#define SQJ_OFF (XTP_OFF + 2 * XTP_BUF)        // 2 x 1024 B
#define INV_OFF (SQJ_OFF + 2048)
#define PART_OFF (INV_OFF + 32)                // 8 warps x 4 x 4B
#define SMEM_TOTAL (PART_OFF + 128)            // ~98.8 KB

__device__ __forceinline__ ull ffma2(ull a, ull b, ull c) {
    ull d; asm("fma.rn.f32x2 %0, %1, %2, %3;" : "=l"(d) : "l"(a), "l"(b), "l"(c)); return d;
}
__device__ __forceinline__ float2 upk(ull v) {
    float2 r; asm("mov.b64 {%0, %1}, %2;" : "=f"(r.x), "=f"(r.y) : "l"(v)); return r;
}
__device__ __forceinline__ float ex2f(float x) {
    float r; asm("ex2.approx.f32 %0, %1;" : "=f"(r) : "f"(x)); return r;
}
__device__ __forceinline__ unsigned pkh2(float a, float b) {
    __half2 h = __floats2half2_rn(a, b);
    return *reinterpret_cast<unsigned*>(&h);
}
__device__ __forceinline__ void stcs4(float* p, float4 v) {
    asm volatile("st.global.cs.v4.f32 [%0], {%1, %2, %3, %4};"
                 :: "l"(p), "f"(v.x), "f"(v.y), "f"(v.z), "f"(v.w) : "memory");
}
__device__ __forceinline__ void cpa8(unsigned dst, const void* src) {
    asm volatile("cp.async.ca.shared.global [%0], [%1], 8;" :: "r"(dst), "l"(src));
}
__device__ __forceinline__ void cpa4(unsigned dst, const void* src) {
    asm volatile("cp.async.ca.shared.global [%0], [%1], 4;" :: "r"(dst), "l"(src));
}
__device__ __forceinline__ void cp_commit() {
    asm volatile("cp.async.commit_group;" ::: "memory");
}
__device__ __forceinline__ void cp_wait0() {
    asm volatile("cp.async.wait_group 0;" ::: "memory");
}

// ---- pre-kernel: g_sqc[idx] = (-log2e/sigma) * ||X[idx]||^2 ----
__global__ void __launch_bounds__(256)
sqc_kernel(const float* __restrict__ X, const float* __restrict__ sigma) {
    int idx = blockIdx.x * 256 + threadIdx.x;          // 0 .. 32767
    const float4* p = reinterpret_cast<const float4*>(X) + (size_t)idx * 4;
    float4 a = p[0], b = p[1], c = p[2], d = p[3];
    float s = a.x * a.x + a.y * a.y + a.z * a.z + a.w * a.w;
    s += b.x * b.x + b.y * b.y + b.z * b.z + b.w * b.w;
    s += c.x * c.x + c.y * c.y + c.z * c.z + c.w * c.w;
    s += d.x * d.x + d.y * d.y + d.z * d.z + d.w * d.w;
    g_sqc[idx] = (-L2E / sigma[0]) * s;
}

__global__ void __launch_bounds__(TT, 2)
GaussianSoftmax_67714454389333_kernel(const float* __restrict__ X,
                                      const float* __restrict__ sigma,
                                      float* __restrict__ out) {
    extern __shared__ char smem_raw[];
    unsigned su;
    asm("{ .reg .u64 t; cvta.to.shared.u64 t, %1; cvt.u32.u64 %0, t; }"
        : "=r"(su) : "l"(smem_raw));

    const int tid = threadIdx.x;
    const int b = blockIdx.y;
    const int i0 = blockIdx.x * RR;
    const int rg4 = (tid >> 7) * 4;        // my 4 rows: rg4..rg4+3
    const int jq = (tid & 127) * 2;        // my 2 cols within the tile

    const float* Xb = X + (size_t)b * NN * FF;

    // ---- constants ----
    const float sg = sigma[0];
    const float cexp = -L2E / sg;
    const float CM2s = -2.0f * cexp;

    // ---- xq: f-paired xi in registers (4 rows x 8 fpairs), plus sic = cexp*sqi ----
    ull xq[8][4];
    float sic[4];
    #pragma unroll
    for (int r = 0; r < 4; ++r) {
        float s = 0.f;
        #pragma unroll
        for (int fp = 0; fp < 8; ++fp) {
            float2 v = *reinterpret_cast<const float2*>(
                &Xb[(size_t)(i0 + rg4 + r) * FF + fp * 2]);
            s = fmaf(v.x, v.x, s);
            s = fmaf(v.y, v.y, s);
            xq[fp][r] = *reinterpret_cast<const ull*>(&v);
        }
        sic[r] = cexp * s;
    }

    // ---- issue tile 0 copy ----
    const int fp_c = tid & 7;              // copy-role: feature pair
    const int jb_c = tid >> 3;             // copy-role: j-row base (0..31)
    {
        unsigned dstb = su + XTP_OFF + fp_c * XTP_ROW;
        const float* srcb = Xb + (size_t)jb_c * FF + fp_c * 2;
        #pragma unroll
        for (int k = 0; k < 8; ++k)
            cpa8(dstb + (jb_c + k * 32) * 8, srcb + (size_t)k * 32 * FF);
        cpa4(su + SQJ_OFF + tid * 4, &g_sqc[b * NN + tid]);
        cp_commit();
    }

    ull acc[4][2];
    #pragma unroll
    for (int r = 0; r < 4; ++r) { acc[r][0] = 0; acc[r][1] = 0; }
    float rsum[4] = {0.f, 0.f, 0.f, 0.f};

    unsigned* h16 = reinterpret_cast<unsigned*>(smem_raw + H16_OFF);

    // ---- main loop over 16 j-tiles (double-buffered cp.async) ----
    #pragma unroll 1
    for (int t = 0; t < NT; ++t) {
        cp_wait0();
        __syncthreads();   // buf[t&1] data visible to all; buf[(t+1)&1] free (compute t-1 done)

        // issue copy of tile t+1 into the other buffer
        if (t + 1 < NT) {
            int buf = (t + 1) & 1;
            unsigned dstb = su + XTP_OFF + buf * XTP_BUF + fp_c * XTP_ROW;
            const float* srcb = Xb + (size_t)(t + 1) * JT * FF + (size_t)jb_c * FF + fp_c * 2;
            #pragma unroll
            for (int k = 0; k < 8; ++k)
                cpa8(dstb + (jb_c + k * 32) * 8, srcb + (size_t)k * 32 * FF);
            cpa4(su + SQJ_OFF + buf * 1024 + tid * 4,
                 &g_sqc[b * NN + (t + 1) * JT + tid]);
            cp_commit();
        }

        // ---- dot products from buf[t&1]: 4 rows x 2 cols, f-paired lanes ----
        const char* xbuf = smem_raw + XTP_OFF + (t & 1) * XTP_BUF;
        #pragma unroll
        for (int fp = 0; fp < 8; ++fp) {
            ulonglong2 xj = *reinterpret_cast<const ulonglong2*>(
                xbuf + fp * XTP_ROW + jq * 8);
            #pragma unroll
            for (int r = 0; r < 4; ++r) {
                acc[r][0] = ffma2(xj.x, xq[fp][r], acc[r][0]);
                acc[r][1] = ffma2(xj.y, xq[fp][r], acc[r][1]);
            }
        }

        // ---- epilogue ----
        {
            float2 sj = *reinterpret_cast<const float2*>(
                smem_raw + SQJ_OFF + (t & 1) * 1024 + jq * 4);
            const int colh = t * (JT / 2) + (jq >> 1);
            #pragma unroll
            for (int r = 0; r < 4; ++r) {
                float2 a0 = upk(acc[r][0]);
                float2 a1 = upk(acc[r][1]);
                float d0 = a0.x + a0.y;
                float d1 = a1.x + a1.y;
                float e0 = fmaf(CM2s, d0, sic[r] + sj.x);
                float e1 = fmaf(CM2s, d1, sic[r] + sj.y);
                float h0 = ex2f(ex2f(e0) * L2E);
                float h1 = ex2f(ex2f(e1) * L2E);
                rsum[r] += h0 + h1;
                h16[(size_t)(rg4 + r) * (NN / 2) + colh] = pkh2(h0, h1);
                acc[r][0] = 0; acc[r][1] = 0;
            }
        }
    }

    // ---- row-sum reduction (8 warps, each covers 4 rows) ----
    float* part = reinterpret_cast<float*>(smem_raw + PART_OFF);   // [8][4]
    #pragma unroll
    for (int r = 0; r < 4; ++r) {
        float v = rsum[r];
        v += __shfl_xor_sync(0xffffffffu, v, 16);
        v += __shfl_xor_sync(0xffffffffu, v, 8);
        v += __shfl_xor_sync(0xffffffffu, v, 4);
        v += __shfl_xor_sync(0xffffffffu, v, 2);
        v += __shfl_xor_sync(0xffffffffu, v, 1);
        if ((tid & 31) == 0) part[(tid >> 5) * 4 + r] = v;
    }
    __syncthreads();
    float* invp = reinterpret_cast<float*>(smem_raw + INV_OFF);
    if (tid < RR) {
        int g = (tid >> 2) * 4, rl = tid & 3;
        float s = part[(g + 0) * 4 + rl] + part[(g + 1) * 4 + rl] +
                  part[(g + 2) * 4 + rl] + part[(g + 3) * 4 + rl];
        invp[tid] = 1.0f / s;
    }
    __syncthreads();

    // ---- phase 2: normalize fp16 h, coalesced streaming STG.128 ----
    float* outB = out + ((size_t)b * NN + i0) * NN;
    #pragma unroll 4
    for (int it = 0; it < (RR * NN / 4) / TT; ++it) {   // 32 iterations
        int c = it * TT + tid;
        int r = c >> 10;                 // 1024 float4 per row
        int j4 = c & 1023;
        float inv = invp[r];
        uint2 v = *reinterpret_cast<const uint2*>(
            smem_raw + H16_OFF + (size_t)r * (NN / 2) * 4 + j4 * 8);
        float2 f0 = __half22float2(*reinterpret_cast<__half2*>(&v.x));
        float2 f1 = __half22float2(*reinterpret_cast<__half2*>(&v.y));
        float4 o = make_float4(f0.x * inv, f0.y * inv, f1.x * inv, f1.y * inv);
        stcs4(&outB[(size_t)r * NN + j4 * 4], o);
    }
}

extern "C" void kernel_launch(void* const* d_in, const int* in_sizes, int n_in,
                              void* d_out, int out_size) {
    const float* X = (const float*)d_in[0];
    const float* sigma = (const float*)d_in[1];
    float* out = (float*)d_out;

    sqc_kernel<<<BB * NN / 256, 256>>>(X, sigma);

    cudaFuncSetAttribute(GaussianSoftmax_67714454389333_kernel,
                         cudaFuncAttributeMaxDynamicSharedMemorySize, SMEM_TOTAL);
    dim3 grid(NN / RR, BB);   // (512, 8)
    GaussianSoftmax_67714454389333_kernel<<<grid, TT, SMEM_TOTAL>>>(X, sigma, out);
}

// round 8
// speedup vs baseline: 1.6243x; 1.2228x over previous
#include <cuda_runtime.h>
#include <cuda_fp16.h>

// GaussianSoftmax: X[8,4096,16], sigma[1] -> softmax(exp(exp(-sqdist/sigma)), axis=2) [8,4096,4096]
//
// R8: tiles fed by cp.async.bulk (UBLKCP) + mbarrier double-buffer instead of
// per-thread LDGSTS. Pre-kernel writes X transposed (g_xt[b][fp][j], float2 entries)
// and cexp*||x_j||^2 (g_sqc), so each j-tile is 8 contiguous 2KB rows + 1KB sqc ->
// 9 bulk copies issued by one elect thread; zero per-thread staging wavefronts.
// Compute unchanged from R7: f-paired f32x2 dot (4 rows x 2 cols/thread), xi in regs,
// h fp16 in smem, fp32 row sums, streaming STG.128 out. T=256, RR=8, 2 CTAs/SM.

#define BB 8
#define NN 4096
#define FF 16
#define RR 8
#define TT 256
#define JT 256
#define NT (NN / JT)
#define L2E 1.4426950408889634f

typedef unsigned long long ull;

__device__ float g_sqc[BB * NN];            // cexp * ||x_j||^2
__device__ float g_xt[BB * FF * NN];        // [b][fp][j] float2: b*65536 + fp*8192 + j*2

// smem byte offsets
#define H16_OFF  0                           // RR x NN/2 uint = 65536
#define XTP_OFF  65536                       // 2 x 16384 (8 fp rows x 2048B, contiguous)
#define XTP_BUF  16384
#define SQJ_OFF  (XTP_OFF + 2 * XTP_BUF)     // 2 x 1024
#define MBAR_OFF (SQJ_OFF + 2048)            // 2 x 8
#define INV_OFF  (MBAR_OFF + 16)
#define PART_OFF (INV_OFF + 32)
#define SMEM_TOTAL (PART_OFF + 128)          // ~98.3 KB -> 2 CTAs/SM

__device__ __forceinline__ ull ffma2(ull a, ull b, ull c) {
    ull d; asm("fma.rn.f32x2 %0, %1, %2, %3;" : "=l"(d) : "l"(a), "l"(b), "l"(c)); return d;
}
__device__ __forceinline__ float2 upk(ull v) {
    float2 r; asm("mov.b64 {%0, %1}, %2;" : "=f"(r.x), "=f"(r.y) : "l"(v)); return r;
}
__device__ __forceinline__ float ex2f(float x) {
    float r; asm("ex2.approx.f32 %0, %1;" : "=f"(r) : "f"(x)); return r;
}
__device__ __forceinline__ unsigned pkh2(float a, float b) {
    __half2 h = __floats2half2_rn(a, b);
    return *reinterpret_cast<unsigned*>(&h);
}
__device__ __forceinline__ void stcs4(float* p, float4 v) {
    asm volatile("st.global.cs.v4.f32 [%0], {%1, %2, %3, %4};"
                 :: "l"(p), "f"(v.x), "f"(v.y), "f"(v.z), "f"(v.w) : "memory");
}
__device__ __forceinline__ void mbar_init(unsigned mbar, unsigned cnt) {
    asm volatile("mbarrier.init.shared.b64 [%0], %1;" :: "r"(mbar), "r"(cnt) : "memory");
}
__device__ __forceinline__ void mbar_expect_tx(unsigned mbar, unsigned tx) {
    asm volatile("mbarrier.arrive.expect_tx.shared.b64 _, [%0], %1;"
                 :: "r"(mbar), "r"(tx) : "memory");
}
__device__ __forceinline__ void bulk_g2s(unsigned dst, const void* src,
                                         unsigned bytes, unsigned mbar) {
    asm volatile("cp.async.bulk.shared::cta.global.mbarrier::complete_tx::bytes "
                 "[%0], [%1], %2, [%3];"
                 :: "r"(dst), "l"(src), "r"(bytes), "r"(mbar) : "memory");
}
__device__ __forceinline__ void mbar_wait(unsigned mbar, unsigned parity) {
    unsigned done;
    asm volatile(
        "{\n\t.reg .pred p;\n\t"
        "mbarrier.try_wait.parity.acquire.cta.shared::cta.b64 p, [%1], %2;\n\t"
        "selp.b32 %0, 1, 0, p;\n\t}"
        : "=r"(done) : "r"(mbar), "r"(parity) : "memory");
    if (!done) {
        asm volatile(
            "{\n\t.reg .pred P1;\n\t"
            "WL_%=:\n\t"
            "mbarrier.try_wait.parity.acquire.cta.shared::cta.b64 P1, [%0], %1, 0x989680;\n\t"
            "@P1 bra.uni WD_%=;\n\t"
            "bra.uni WL_%=;\n\t"
            "WD_%=:\n\t}"
            :: "r"(mbar), "r"(parity) : "memory");
    }
}

// ---- pre-kernel: transpose X into f-pair rows + cexp*||x_j||^2 ----
__global__ void __launch_bounds__(256)
prep_kernel(const float* __restrict__ X, const float* __restrict__ sigma) {
    int idx = blockIdx.x * 256 + threadIdx.x;          // b*4096 + j, 0..32767
    int b = idx >> 12, j = idx & 4095;
    const float4* p = reinterpret_cast<const float4*>(X) + (size_t)idx * 4;
    float s = 0.f;
    float2* xtb = reinterpret_cast<float2*>(&g_xt[b * 65536]) + j;   // + fp*4096
    #pragma unroll
    for (int q = 0; q < 4; ++q) {
        float4 v = p[q];
        s += v.x * v.x + v.y * v.y + v.z * v.z + v.w * v.w;
        xtb[(2 * q + 0) * 4096] = make_float2(v.x, v.y);
        xtb[(2 * q + 1) * 4096] = make_float2(v.z, v.w);
    }
    g_sqc[idx] = (-L2E / sigma[0]) * s;
}

__global__ void __launch_bounds__(TT, 2)
GaussianSoftmax_67714454389333_kernel(const float* __restrict__ X,
                                      const float* __restrict__ sigma,
                                      float* __restrict__ out) {
    extern __shared__ char smem_raw[];
    unsigned su;
    asm("{ .reg .u64 t; cvta.to.shared.u64 t, %1; cvt.u32.u64 %0, t; }"
        : "=r"(su) : "l"(smem_raw));

    const int tid = threadIdx.x;
    const int b = blockIdx.y;
    const int i0 = blockIdx.x * RR;
    const int rg4 = (tid >> 7) * 4;        // my 4 rows
    const int jq = (tid & 127) * 2;        // my 2 cols within the tile

    const float* Xb = X + (size_t)b * NN * FF;

    const float sg = sigma[0];
    const float cexp = -L2E / sg;
    const float CM2s = -2.0f * cexp;

    // ---- xq: f-paired xi in registers (4 rows x 8 fpairs) + sic = cexp*sqi ----
    ull xq[8][4];
    float sic[4];
    #pragma unroll
    for (int r = 0; r < 4; ++r) {
        float s = 0.f;
        #pragma unroll
        for (int fp = 0; fp < 8; ++fp) {
            float2 v = *reinterpret_cast<const float2*>(
                &Xb[(size_t)(i0 + rg4 + r) * FF + fp * 2]);
            s = fmaf(v.x, v.x, s);
            s = fmaf(v.y, v.y, s);
            xq[fp][r] = *reinterpret_cast<const ull*>(&v);
        }
        sic[r] = cexp * s;
    }

    // ---- mbarrier setup + tile 0 copy ----
    const float* xtB = &g_xt[b * 65536];
    const float* sqB = &g_sqc[b * NN];
    const unsigned mb0 = su + MBAR_OFF, mb1 = su + MBAR_OFF + 8;
    if (tid == 0) {
        mbar_init(mb0, 1);
        mbar_init(mb1, 1);
        asm volatile("fence.proxy.async.shared::cta;" ::: "memory");
    }
    __syncthreads();
    if (tid == 0) {
        mbar_expect_tx(mb0, 8 * 2048 + 1024);
        #pragma unroll
        for (int fp = 0; fp < 8; ++fp)
            bulk_g2s(su + XTP_OFF + fp * 2048, xtB + fp * 8192, 2048, mb0);
        bulk_g2s(su + SQJ_OFF, sqB, 1024, mb0);
    }

    ull acc[4][2];
    #pragma unroll
    for (int r = 0; r < 4; ++r) { acc[r][0] = 0; acc[r][1] = 0; }
    float rsum[4] = {0.f, 0.f, 0.f, 0.f};
    unsigned* h16 = reinterpret_cast<unsigned*>(smem_raw + H16_OFF);
    unsigned ph0 = 0, ph1 = 0;

    // ---- main loop over 16 j-tiles (mbarrier double-buffer) ----
    #pragma unroll 1
    for (int t = 0; t < NT; ++t) {
        __syncthreads();   // buf[(t+1)&1] fully consumed (compute t-1 done by all)

        if (tid == 0 && t + 1 < NT) {
            int buf = (t + 1) & 1;
            unsigned mb = buf ? mb1 : mb0;
            mbar_expect_tx(mb, 8 * 2048 + 1024);
            const float* src = xtB + (t + 1) * (JT * 2);
            #pragma unroll
            for (int fp = 0; fp < 8; ++fp)
                bulk_g2s(su + XTP_OFF + buf * XTP_BUF + fp * 2048,
                         src + fp * 8192, 2048, mb);
            bulk_g2s(su + SQJ_OFF + buf * 1024, sqB + (t + 1) * JT, 1024, mb);
        }

        // wait for tile t (issued last iteration / prologue)
        if (t & 1) { mbar_wait(mb1, ph1); ph1 ^= 1; }
        else       { mbar_wait(mb0, ph0); ph0 ^= 1; }

        // ---- dot products: 4 rows x 2 cols, f-paired lanes ----
        const char* xbuf = smem_raw + XTP_OFF + (t & 1) * XTP_BUF;
        #pragma unroll
        for (int fp = 0; fp < 8; ++fp) {
            ulonglong2 xj = *reinterpret_cast<const ulonglong2*>(
                xbuf + fp * 2048 + jq * 8);
            #pragma unroll
            for (int r = 0; r < 4; ++r) {
                acc[r][0] = ffma2(xj.x, xq[fp][r], acc[r][0]);
                acc[r][1] = ffma2(xj.y, xq[fp][r], acc[r][1]);
            }
        }

        // ---- epilogue ----
        {
            float2 sj = *reinterpret_cast<const float2*>(
                smem_raw + SQJ_OFF + (t & 1) * 1024 + jq * 4);
            const int colh = t * (JT / 2) + (jq >> 1);
            #pragma unroll
            for (int r = 0; r < 4; ++r) {
                float2 a0 = upk(acc[r][0]);
                float2 a1 = upk(acc[r][1]);
                float e0 = fmaf(CM2s, a0.x + a0.y, sic[r] + sj.x);
                float e1 = fmaf(CM2s, a1.x + a1.y, sic[r] + sj.y);
                float h0 = ex2f(ex2f(e0) * L2E);
                float h1 = ex2f(ex2f(e1) * L2E);
                rsum[r] += h0 + h1;
                h16[(size_t)(rg4 + r) * (NN / 2) + colh] = pkh2(h0, h1);
                acc[r][0] = 0; acc[r][1] = 0;
            }
        }
    }

    // ---- row-sum reduction ----
    float* part = reinterpret_cast<float*>(smem_raw + PART_OFF);   // [8][4]
    #pragma unroll
    for (int r = 0; r < 4; ++r) {
        float v = rsum[r];
        v += __shfl_xor_sync(0xffffffffu, v, 16);
        v += __shfl_xor_sync(0xffffffffu, v, 8);
        v += __shfl_xor_sync(0xffffffffu, v, 4);
        v += __shfl_xor_sync(0xffffffffu, v, 2);
        v += __shfl_xor_sync(0xffffffffu, v, 1);
        if ((tid & 31) == 0) part[(tid >> 5) * 4 + r] = v;
    }
    __syncthreads();
    float* invp = reinterpret_cast<float*>(smem_raw + INV_OFF);
    if (tid < RR) {
        int g = (tid >> 2) * 4, rl = tid & 3;
        float s = part[(g + 0) * 4 + rl] + part[(g + 1) * 4 + rl] +
                  part[(g + 2) * 4 + rl] + part[(g + 3) * 4 + rl];
        invp[tid] = 1.0f / s;
    }
    __syncthreads();

    // ---- phase 2: normalize fp16 h, coalesced streaming STG.128 ----
    float* outB = out + ((size_t)b * NN + i0) * NN;
    #pragma unroll 4
    for (int it = 0; it < (RR * NN / 4) / TT; ++it) {   // 32 iterations
        int c = it * TT + tid;
        int r = c >> 10;
        int j4 = c & 1023;
        float inv = invp[r];
        uint2 v = *reinterpret_cast<const uint2*>(
            smem_raw + H16_OFF + (size_t)r * (NN / 2) * 4 + j4 * 8);
        float2 f0 = __half22float2(*reinterpret_cast<__half2*>(&v.x));
        float2 f1 = __half22float2(*reinterpret_cast<__half2*>(&v.y));
        float4 o = make_float4(f0.x * inv, f0.y * inv, f1.x * inv, f1.y * inv);
        stcs4(&outB[(size_t)r * NN + j4 * 4], o);
    }
}

extern "C" void kernel_launch(void* const* d_in, const int* in_sizes, int n_in,
                              void* d_out, int out_size) {
    const float* X = (const float*)d_in[0];
    const float* sigma = (const float*)d_in[1];
    float* out = (float*)d_out;

    prep_kernel<<<BB * NN / 256, 256>>>(X, sigma);

    cudaFuncSetAttribute(GaussianSoftmax_67714454389333_kernel,
                         cudaFuncAttributeMaxDynamicSharedMemorySize, SMEM_TOTAL);
    dim3 grid(NN / RR, BB);   // (512, 8)
    GaussianSoftmax_67714454389333_kernel<<<grid, TT, SMEM_TOTAL>>>(X, sigma, out);
}